// round 3
// baseline (speedup 1.0000x reference)
#include <cuda_runtime.h>
#include <cuda_bf16.h>
#include <cstdint>

#define DIM 256
#define KSZ 8
#define MAXC 2048

__device__ float g_sq[MAXC];
__device__ float g_pc[MAXC];
__device__ float g_an_total;
__device__ __nv_bfloat16 g_hi[MAXC * DIM];
__device__ __nv_bfloat16 g_lo[MAXC * DIM];

// ---------------------------------------------------------------------------
// Kernel 1: ONE WARP PER CLASS. Lane owns 8 dims x 8 rows in registers.
// No shared memory, no syncthreads — only shfl reductions.
// ---------------------------------------------------------------------------
__global__ void __launch_bounds__(256) centers_kernel(const float* __restrict__ in) {
    int tid  = threadIdx.x;
    int lane = tid & 31;
    int c    = (blockIdx.x * blockDim.x + tid) >> 5;   // class id

    if (blockIdx.x == 0 && tid == 0) g_an_total = 0.f;

    const float* base = in + (size_t)c * KSZ * DIM + lane * 8;

    // Load 8 rows x 8 dims (two float4 per row) — all issued up front (MLP=16)
    float v[8][8];
#pragma unroll
    for (int k = 0; k < 8; k++) {
        float4 a = *(const float4*)(base + (size_t)k * DIM);
        float4 b = *(const float4*)(base + (size_t)k * DIM + 4);
        v[k][0] = a.x; v[k][1] = a.y; v[k][2] = a.z; v[k][3] = a.w;
        v[k][4] = b.x; v[k][5] = b.y; v[k][6] = b.z; v[k][7] = b.w;
    }

    // Row inverse norms
    float invn[8];
#pragma unroll
    for (int k = 0; k < 8; k++) {
        float ss = 0.f;
#pragma unroll
        for (int j = 0; j < 8; j++) ss = fmaf(v[k][j], v[k][j], ss);
#pragma unroll
        for (int o = 16; o > 0; o >>= 1) ss += __shfl_xor_sync(0xffffffffu, ss, o);
        invn[k] = rsqrtf(ss);
    }

    // Center for this lane's 8 dims (fully local — no transpose needed)
    float cd[8];
#pragma unroll
    for (int j = 0; j < 8; j++) {
        float s = 0.f;
#pragma unroll
        for (int k = 0; k < 8; k++) s = fmaf(v[k][j], invn[k], s);
        cd[j] = s * 0.125f;
    }

    // ||center||^2
    float s2 = 0.f;
#pragma unroll
    for (int j = 0; j < 8; j++) s2 = fmaf(cd[j], cd[j], s2);
#pragma unroll
    for (int o = 16; o > 0; o >>= 1) s2 += __shfl_xor_sync(0xffffffffu, s2, o);
    if (lane == 0) g_sq[c] = s2;
    float icn = rsqrtf(s2);

    // hi/lo bf16 split, coalesced 16B stores
    __nv_bfloat16 hb[8], lb[8];
#pragma unroll
    for (int j = 0; j < 8; j++) {
        hb[j] = __float2bfloat16(cd[j]);
        lb[j] = __float2bfloat16(cd[j] - __bfloat162float(hb[j]));
    }
    *(uint4*)(g_hi + (size_t)c * DIM + lane * 8) = *(uint4*)hb;
    *(uint4*)(g_lo + (size_t)c * DIM + lane * 8) = *(uint4*)lb;

    // dist_pc per row: ||x_k - cn|| = sqrt(2 - 2 * invn[k]*icn*dot(raw_k, center))
    float pc = 0.f;
#pragma unroll
    for (int k = 0; k < 8; k++) {
        float dot = 0.f;
#pragma unroll
        for (int j = 0; j < 8; j++) dot = fmaf(v[k][j], cd[j], dot);
#pragma unroll
        for (int o = 16; o > 0; o >>= 1) dot += __shfl_xor_sync(0xffffffffu, dot, o);
        float d = invn[k] * icn * dot;
        pc += sqrtf(fmaxf(2.f - 2.f * d, 0.f));
    }
    if (lane == 0) g_pc[c] = pc;
}

// ---------------------------------------------------------------------------
// cp.async helpers
// ---------------------------------------------------------------------------
__device__ __forceinline__ void cp16(uint32_t smem_addr, const void* gptr) {
    asm volatile("cp.async.cg.shared.global [%0], [%1], 16;\n"
                 :: "r"(smem_addr), "l"(gptr));
}

// ---------------------------------------------------------------------------
// Kernel 2: upper-triangle tensor-core Gram GEMM, cp.async double-buffered,
// fused hinge, single atomicAdd per block into g_an_total.
// G = H·H^T + L·H^T (concat K=512). 64x64 tile, 128 threads (2x2 warps).
// ---------------------------------------------------------------------------
__global__ void __launch_bounds__(128) mma_hinge(int C) {
    __shared__ __align__(16) __nv_bfloat16 As[2][64][72];
    __shared__ __align__(16) __nv_bfloat16 Bs[2][64][72];
    __shared__ float warp_sums[4];

    int tid  = threadIdx.x;
    int warp = tid >> 5;
    int lane = tid & 31;

    // linear block id -> upper-triangle (bi, bj), bi <= bj
    int NB = C >> 6;                  // 16
    int bi = 0, rem = blockIdx.x;
    while (rem >= NB - bi) { rem -= NB - bi; bi++; }
    int bj = bi + rem;
    int i0 = bi * 64;
    int j0 = bj * 64;
    bool diag = (bi == bj);

    int wr = warp >> 1;
    int wc = warp & 1;

    float acc[2][4][4] = {};

    auto load_chunk = [&](int kchunk, int buf) {
        const __nv_bfloat16* srcA = (kchunk < 4) ? g_hi : g_lo;
        int k0 = (kchunk & 3) * 64;
#pragma unroll
        for (int vv = 0; vv < 4; vv++) {
            int idx = tid + vv * 128;
            int r = idx >> 3;
            int q = idx & 7;
            cp16((uint32_t)__cvta_generic_to_shared(&As[buf][r][q * 8]),
                 srcA + (size_t)(i0 + r) * DIM + k0 + q * 8);
            cp16((uint32_t)__cvta_generic_to_shared(&Bs[buf][r][q * 8]),
                 g_hi + (size_t)(j0 + r) * DIM + k0 + q * 8);
        }
        asm volatile("cp.async.commit_group;\n" ::: "memory");
    };

    load_chunk(0, 0);

    for (int kc = 0; kc < 8; kc++) {
        if (kc < 7) {
            load_chunk(kc + 1, (kc + 1) & 1);
            asm volatile("cp.async.wait_group 1;\n" ::: "memory");
        } else {
            asm volatile("cp.async.wait_group 0;\n" ::: "memory");
        }
        __syncthreads();

        int buf = kc & 1;
#pragma unroll
        for (int kk = 0; kk < 64; kk += 16) {
            uint32_t afr[2][4];
#pragma unroll
            for (int mi = 0; mi < 2; mi++) {
                int row = wr * 32 + mi * 16 + (lane & 15);
                int col = kk + (lane >> 4) * 8;
                uint32_t addr = (uint32_t)__cvta_generic_to_shared(&As[buf][row][col]);
                asm volatile("ldmatrix.sync.aligned.m8n8.x4.shared.b16 {%0,%1,%2,%3}, [%4];"
                    : "=r"(afr[mi][0]), "=r"(afr[mi][1]), "=r"(afr[mi][2]), "=r"(afr[mi][3])
                    : "r"(addr));
            }
            uint32_t bfr[4][2];
#pragma unroll
            for (int nq = 0; nq < 2; nq++) {
                int row = wc * 32 + nq * 16 + ((lane >> 3) & 1) * 8 + (lane & 7);
                int col = kk + (lane >> 4) * 8;
                uint32_t addr = (uint32_t)__cvta_generic_to_shared(&Bs[buf][row][col]);
                uint32_t r0, r1, r2, r3;
                asm volatile("ldmatrix.sync.aligned.m8n8.x4.shared.b16 {%0,%1,%2,%3}, [%4];"
                    : "=r"(r0), "=r"(r1), "=r"(r2), "=r"(r3) : "r"(addr));
                bfr[nq * 2 + 0][0] = r0; bfr[nq * 2 + 0][1] = r2;
                bfr[nq * 2 + 1][0] = r1; bfr[nq * 2 + 1][1] = r3;
            }
#pragma unroll
            for (int mi = 0; mi < 2; mi++)
#pragma unroll
                for (int nj = 0; nj < 4; nj++) {
                    asm volatile(
                        "mma.sync.aligned.m16n8k16.row.col.f32.bf16.bf16.f32 "
                        "{%0,%1,%2,%3}, {%4,%5,%6,%7}, {%8,%9}, {%0,%1,%2,%3};"
                        : "+f"(acc[mi][nj][0]), "+f"(acc[mi][nj][1]),
                          "+f"(acc[mi][nj][2]), "+f"(acc[mi][nj][3])
                        : "r"(afr[mi][0]), "r"(afr[mi][1]), "r"(afr[mi][2]), "r"(afr[mi][3]),
                          "r"(bfr[nj][0]), "r"(bfr[nj][1]));
                }
        }
        __syncthreads();
    }

    // Hinge epilogue: just sum everything (grand total is all we need).
    // c-frag: c0,c1 -> (row=lane>>2, col=(lane&3)*2+{0,1}); c2,c3 -> row+8
    int qr = lane >> 2;
    int qc = lane & 3;
    float s = 0.f;
#pragma unroll
    for (int mi = 0; mi < 2; mi++)
#pragma unroll
        for (int h = 0; h < 2; h++) {
            int i = i0 + wr * 32 + mi * 16 + h * 8 + qr;
            float sqi = g_sq[i];
#pragma unroll
            for (int nj = 0; nj < 4; nj++)
#pragma unroll
                for (int e = 0; e < 2; e++) {
                    int j = j0 + wc * 32 + nj * 8 + qc * 2 + e;
                    float d2 = sqi + g_sq[j] - 2.f * acc[mi][nj][h * 2 + e];
                    float d  = sqrtf(fmaxf(d2, 1e-12f));
                    float hh = fmaxf(0.7f - d, 0.f);
                    if (!diag || i != j) s += hh;
                }
        }
    if (!diag) s *= 2.f;   // off-diagonal tiles count both (i,j) and (j,i)

#pragma unroll
    for (int o = 16; o > 0; o >>= 1) s += __shfl_xor_sync(0xffffffffu, s, o);
    if (lane == 0) warp_sums[warp] = s;
    __syncthreads();
    if (tid == 0) {
        float t = warp_sums[0] + warp_sums[1] + warp_sums[2] + warp_sums[3];
        atomicAdd(&g_an_total, t);
    }
}

// ---------------------------------------------------------------------------
// Kernel 3: final reduction
// ---------------------------------------------------------------------------
__global__ void __launch_bounds__(256) finalize_kernel(float* __restrict__ out, int n, int C) {
    int tid  = threadIdx.x;
    int w    = tid >> 5;
    int lane = tid & 31;
    __shared__ float sp[8];

    float p = 0.f;
    for (int i = tid; i < C; i += 256) p += g_pc[i];
#pragma unroll
    for (int o = 16; o > 0; o >>= 1) p += __shfl_xor_sync(0xffffffffu, p, o);
    if (lane == 0) sp[w] = p;
    __syncthreads();
    if (tid == 0) {
        float P = 0.f;
#pragma unroll
        for (int k = 0; k < 8; k++) P += sp[k];
        float pc_mean = P / (float)n;
        float an_mean = g_an_total / ((float)C * (float)(C - 1));
        out[0] = pc_mean + an_mean;
        out[1] = pc_mean;
        out[2] = an_mean;
    }
}

extern "C" void kernel_launch(void* const* d_in, const int* in_sizes, int n_in,
                              void* d_out, int out_size) {
    const float* in = (const float*)d_in[0];
    int n = in_sizes[0] / DIM;   // 8192
    int C = n / KSZ;             // 1024
    int NB = C / 64;             // 16

    centers_kernel<<<C / 8, 256>>>(in);            // warp per class
    mma_hinge<<<NB * (NB + 1) / 2, 128>>>(C);      // 136 blocks, upper triangle
    finalize_kernel<<<1, 256>>>((float*)d_out, n, C);
}

// round 4
// speedup vs baseline: 1.5581x; 1.5581x over previous
#include <cuda_runtime.h>
#include <cuda_bf16.h>
#include <cstdint>

#define DIM 256
#define KSZ 8
#define MAXC 2048

__device__ float g_sq[MAXC];
__device__ float g_pc[MAXC];
__device__ float g_an_total;
__device__ __nv_bfloat16 g_hi[MAXC * DIM];
__device__ __nv_bfloat16 g_lo[MAXC * DIM];

// ---------------------------------------------------------------------------
// Kernel 1: block per class (K=8 rows), 256 threads = 8 warps. (round-1 proven
// structure, float4 global loads/stores)
// ---------------------------------------------------------------------------
__global__ void __launch_bounds__(256) centers_kernel(const float* __restrict__ in) {
    int c    = blockIdx.x;
    int tid  = threadIdx.x;
    int w    = tid >> 5;
    int lane = tid & 31;

    if (c == 0 && tid == 0) g_an_total = 0.f;

    __shared__ float raw[KSZ][DIM];
    __shared__ float invn[KSZ];
    __shared__ float cen[DIM];
    __shared__ float redA[KSZ];
    __shared__ float redB[KSZ];

    const float* rowp = in + (size_t)(c * KSZ + w) * DIM + lane * 8;

    // warp w loads row w: lane owns dims [lane*8, lane*8+8)
    float v[8];
    {
        float4 a = *(const float4*)(rowp);
        float4 b = *(const float4*)(rowp + 4);
        v[0]=a.x; v[1]=a.y; v[2]=a.z; v[3]=a.w;
        v[4]=b.x; v[5]=b.y; v[6]=b.z; v[7]=b.w;
        *(float4*)&raw[w][lane * 8]     = a;
        *(float4*)&raw[w][lane * 8 + 4] = b;
    }
    float ss = 0.f;
#pragma unroll
    for (int j = 0; j < 8; j++) ss = fmaf(v[j], v[j], ss);
#pragma unroll
    for (int o = 16; o > 0; o >>= 1) ss += __shfl_xor_sync(0xffffffffu, ss, o);
    if (lane == 0) invn[w] = rsqrtf(ss);
    __syncthreads();

    // thread t owns dim t
    float cd = 0.f;
#pragma unroll
    for (int k = 0; k < 8; k++) cd = fmaf(raw[k][tid], invn[k], cd);
    cd *= 0.125f;
    cen[tid] = cd;

    __nv_bfloat16 hb = __float2bfloat16(cd);
    g_hi[(size_t)c * DIM + tid] = hb;
    g_lo[(size_t)c * DIM + tid] = __float2bfloat16(cd - __bfloat162float(hb));

    float s2 = cd * cd;
#pragma unroll
    for (int o = 16; o > 0; o >>= 1) s2 += __shfl_xor_sync(0xffffffffu, s2, o);
    if (lane == 0) redA[w] = s2;
    __syncthreads();

    float sqc = 0.f;
#pragma unroll
    for (int k = 0; k < 8; k++) sqc += redA[k];
    if (tid == 0) g_sq[c] = sqc;
    float icn = rsqrtf(sqc);

    // dot(x_w, cen) using registers v (dims lane*8..lane*8+7)
    float dot = 0.f;
#pragma unroll
    for (int j = 0; j < 8; j++) dot = fmaf(v[j], cen[lane * 8 + j], dot);
#pragma unroll
    for (int o = 16; o > 0; o >>= 1) dot += __shfl_xor_sync(0xffffffffu, dot, o);
    if (lane == 0) {
        float d = invn[w] * icn * dot;
        redB[w] = sqrtf(fmaxf(2.f - 2.f * d, 0.f));
    }
    __syncthreads();
    if (tid == 0) {
        float p = 0.f;
#pragma unroll
        for (int k = 0; k < 8; k++) p += redB[k];
        g_pc[c] = p;
    }
}

__device__ __forceinline__ void cp16(uint32_t smem_addr, const void* gptr) {
    asm volatile("cp.async.cg.shared.global [%0], [%1], 16;\n"
                 :: "r"(smem_addr), "l"(gptr));
}

// ---------------------------------------------------------------------------
// Kernel 2: upper-triangle Gram GEMM, 256 threads = 8 warps (2 row x 4 col),
// warp tile 32x16, cp.async double-buffered, fused hinge, one atomic/block.
// G = H·H^T + L·H^T (concat K=512).
// ---------------------------------------------------------------------------
__global__ void __launch_bounds__(256) mma_hinge(int C) {
    __shared__ __align__(16) __nv_bfloat16 As[2][64][72];
    __shared__ __align__(16) __nv_bfloat16 Bs[2][64][72];
    __shared__ float sqi_s[64], sqj_s[64];
    __shared__ float warp_sums[8];

    int tid  = threadIdx.x;
    int warp = tid >> 5;
    int lane = tid & 31;

    int NB = C >> 6;
    int bi = 0, rem = blockIdx.x;
    while (rem >= NB - bi) { rem -= NB - bi; bi++; }
    int bj = bi + rem;
    int i0 = bi * 64;
    int j0 = bj * 64;
    bool diag = (bi == bj);

    int wr = warp >> 2;   // 0..1 : 32-row group
    int wc = warp & 3;    // 0..3 : 16-col group

    float acc[2][2][4] = {};   // [mi][nj][4]

    auto load_chunk = [&](int kchunk, int buf) {
        const __nv_bfloat16* srcA = (kchunk < 4) ? g_hi : g_lo;
        int k0 = (kchunk & 3) * 64;
#pragma unroll
        for (int vv = 0; vv < 2; vv++) {
            int idx = tid + vv * 256;      // 0..511
            int r = idx >> 3;
            int q = idx & 7;
            cp16((uint32_t)__cvta_generic_to_shared(&As[buf][r][q * 8]),
                 srcA + (size_t)(i0 + r) * DIM + k0 + q * 8);
            cp16((uint32_t)__cvta_generic_to_shared(&Bs[buf][r][q * 8]),
                 g_hi + (size_t)(j0 + r) * DIM + k0 + q * 8);
        }
        asm volatile("cp.async.commit_group;\n" ::: "memory");
    };

    load_chunk(0, 0);
    // preload g_sq while first chunk is in flight
    if (tid < 64)       sqi_s[tid]       = g_sq[i0 + tid];
    else if (tid < 128) sqj_s[tid - 64]  = g_sq[j0 + tid - 64];

    for (int kc = 0; kc < 8; kc++) {
        if (kc < 7) {
            load_chunk(kc + 1, (kc + 1) & 1);
            asm volatile("cp.async.wait_group 1;\n" ::: "memory");
        } else {
            asm volatile("cp.async.wait_group 0;\n" ::: "memory");
        }
        __syncthreads();

        int buf = kc & 1;
#pragma unroll
        for (int kk = 0; kk < 64; kk += 16) {
            uint32_t afr[2][4];
#pragma unroll
            for (int mi = 0; mi < 2; mi++) {
                int row = wr * 32 + mi * 16 + (lane & 15);
                int col = kk + (lane >> 4) * 8;
                uint32_t addr = (uint32_t)__cvta_generic_to_shared(&As[buf][row][col]);
                asm volatile("ldmatrix.sync.aligned.m8n8.x4.shared.b16 {%0,%1,%2,%3}, [%4];"
                    : "=r"(afr[mi][0]), "=r"(afr[mi][1]), "=r"(afr[mi][2]), "=r"(afr[mi][3])
                    : "r"(addr));
            }
            uint32_t bfr[2][2];
            {
                int row = wc * 16 + ((lane >> 3) & 1) * 8 + (lane & 7);
                int col = kk + (lane >> 4) * 8;
                uint32_t addr = (uint32_t)__cvta_generic_to_shared(&Bs[buf][row][col]);
                uint32_t r0, r1, r2, r3;
                asm volatile("ldmatrix.sync.aligned.m8n8.x4.shared.b16 {%0,%1,%2,%3}, [%4];"
                    : "=r"(r0), "=r"(r1), "=r"(r2), "=r"(r3) : "r"(addr));
                bfr[0][0] = r0; bfr[0][1] = r2;
                bfr[1][0] = r1; bfr[1][1] = r3;
            }
#pragma unroll
            for (int mi = 0; mi < 2; mi++)
#pragma unroll
                for (int nj = 0; nj < 2; nj++) {
                    asm volatile(
                        "mma.sync.aligned.m16n8k16.row.col.f32.bf16.bf16.f32 "
                        "{%0,%1,%2,%3}, {%4,%5,%6,%7}, {%8,%9}, {%0,%1,%2,%3};"
                        : "+f"(acc[mi][nj][0]), "+f"(acc[mi][nj][1]),
                          "+f"(acc[mi][nj][2]), "+f"(acc[mi][nj][3])
                        : "r"(afr[mi][0]), "r"(afr[mi][1]), "r"(afr[mi][2]), "r"(afr[mi][3]),
                          "r"(bfr[nj][0]), "r"(bfr[nj][1]));
                }
        }
        __syncthreads();
    }

    // hinge epilogue -> grand total only
    int qr = lane >> 2;
    int qc = lane & 3;
    float s = 0.f;
#pragma unroll
    for (int mi = 0; mi < 2; mi++)
#pragma unroll
        for (int h = 0; h < 2; h++) {
            int ii = wr * 32 + mi * 16 + h * 8 + qr;
            float sqi = sqi_s[ii];
            int i = i0 + ii;
#pragma unroll
            for (int nj = 0; nj < 2; nj++)
#pragma unroll
                for (int e = 0; e < 2; e++) {
                    int jj = wc * 16 + nj * 8 + qc * 2 + e;
                    int j = j0 + jj;
                    float d2 = sqi + sqj_s[jj] - 2.f * acc[mi][nj][h * 2 + e];
                    float d  = sqrtf(fmaxf(d2, 1e-12f));
                    float hh = fmaxf(0.7f - d, 0.f);
                    if (!diag || i != j) s += hh;
                }
        }
    if (!diag) s *= 2.f;

#pragma unroll
    for (int o = 16; o > 0; o >>= 1) s += __shfl_xor_sync(0xffffffffu, s, o);
    if (lane == 0) warp_sums[warp] = s;
    __syncthreads();
    if (tid == 0) {
        float t = 0.f;
#pragma unroll
        for (int k = 0; k < 8; k++) t += warp_sums[k];
        atomicAdd(&g_an_total, t);
    }
}

// ---------------------------------------------------------------------------
__global__ void __launch_bounds__(256) finalize_kernel(float* __restrict__ out, int n, int C) {
    int tid  = threadIdx.x;
    int w    = tid >> 5;
    int lane = tid & 31;
    __shared__ float sp[8];

    float p = 0.f;
    for (int i = tid; i < C; i += 256) p += g_pc[i];
#pragma unroll
    for (int o = 16; o > 0; o >>= 1) p += __shfl_xor_sync(0xffffffffu, p, o);
    if (lane == 0) sp[w] = p;
    __syncthreads();
    if (tid == 0) {
        float P = 0.f;
#pragma unroll
        for (int k = 0; k < 8; k++) P += sp[k];
        float pc_mean = P / (float)n;
        float an_mean = g_an_total / ((float)C * (float)(C - 1));
        out[0] = pc_mean + an_mean;
        out[1] = pc_mean;
        out[2] = an_mean;
    }
}

extern "C" void kernel_launch(void* const* d_in, const int* in_sizes, int n_in,
                              void* d_out, int out_size) {
    const float* in = (const float*)d_in[0];
    int n = in_sizes[0] / DIM;   // 8192
    int C = n / KSZ;             // 1024
    int NB = C / 64;             // 16

    centers_kernel<<<C, 256>>>(in);
    mma_hinge<<<NB * (NB + 1) / 2, 256>>>(C);   // 136 blocks, upper triangle
    finalize_kernel<<<1, 256>>>((float*)d_out, n, C);
}